// round 11
// baseline (speedup 1.0000x reference)
#include <cuda_runtime.h>
#include <cuda_bf16.h>

#define N_NODES 100000
#define N_EDGES 1600000
#define IN_DIM  128
#define HID_DIM 64
#define OUT_DIM 40
#define SCAN_T  1024
#define GRP     8
#define NGROUPS (N_EDGES / GRP)        // 200000, exact

// ---------------- scratch (static device globals; no runtime alloc) --------
__device__              int    g_is64;
__device__              int    g_cnt [N_NODES];      // in-degree (edges only)
__device__              int    g_rs  [N_NODES + 1];  // CSR row start
__device__              int    g_cur [N_NODES];      // fill cursor
__device__ __align__(16) float g_dinv[N_NODES];
__device__              int    g_src [N_EDGES];
__device__              int    g_dst [N_EDGES];
__device__ __align__(16) int4  g_csr [N_EDGES];      // {src, dst, bits(norm), 0} sorted by dst
__device__ __align__(16) float g_h1  [(size_t)N_NODES * HID_DIM];   // x@W1
__device__ __align__(16) float g_agg1[(size_t)N_NODES * HID_DIM];   // layer1 agg
__device__ __align__(16) float g_h2  [(size_t)N_NODES * OUT_DIM];   // relu(agg1+b1)@W2

__device__ __forceinline__ void redg_v4(float* p, float a, float b, float c, float d) {
    asm volatile("red.global.add.v4.f32 [%0], {%1, %2, %3, %4};"
                 :: "l"(p), "f"(a), "f"(b), "f"(c), "f"(d) : "memory");
}

// ---------------- dtype detection: int32 vs int64 edge_index ---------------
__global__ void k_detect(const unsigned* __restrict__ w) {
    if (threadIdx.x == 0 && blockIdx.x == 0) {
        int all0 = 1;
        for (int i = 0; i < 64; i++)
            if (w[2 * i + 1] != 0u) { all0 = 0; break; }
        g_is64 = all0;
    }
}

__global__ void k_zero_cnt() {
    int i = blockIdx.x * blockDim.x + threadIdx.x;
    if (i < N_NODES) g_cnt[i] = 0;
}

// extract src/dst as int32 (either stored width) + histogram by dst
__global__ void k_extract(const unsigned* __restrict__ w) {
    int e = blockIdx.x * blockDim.x + threadIdx.x;
    if (e >= N_EDGES) return;
    int s, d;
    if (g_is64) {
        s = (int)w[2 * e];                           // low word of int64
        d = (int)w[2 * (N_EDGES + e)];
    } else {
        s = (int)w[e];
        d = (int)w[N_EDGES + e];
    }
    g_src[e] = s;
    g_dst[e] = d;
    atomicAdd(&g_cnt[d], 1);
}

__global__ void k_rsqrt() {
    int i = blockIdx.x * blockDim.x + threadIdx.x;
    if (i < N_NODES) g_dinv[i] = rsqrtf((float)g_cnt[i] + 1.0f);  // + self loop
}

// single-block exclusive scan of g_cnt -> g_rs / g_cur
__global__ __launch_bounds__(SCAN_T) void k_scan() {
    __shared__ int part[SCAN_T];
    int t = threadIdx.x;
    const int chunk = (N_NODES + SCAN_T - 1) / SCAN_T;
    int lo = t * chunk;
    int hi = min(lo + chunk, N_NODES);
    int sum = 0;
    for (int i = lo; i < hi; i++) sum += g_cnt[i];
    part[t] = sum;
    __syncthreads();
    for (int off = 1; off < SCAN_T; off <<= 1) {
        int other = (t >= off) ? part[t - off] : 0;
        __syncthreads();
        part[t] += other;
        __syncthreads();
    }
    int run = part[t] - sum;
    for (int i = lo; i < hi; i++) {
        g_rs[i]  = run;
        g_cur[i] = run;
        run += g_cnt[i];
    }
    if (t == SCAN_T - 1) g_rs[N_NODES] = run;
}

// scatter edges into CSR slots (sorted by dst), norm precomputed
__global__ void k_fill() {
    int e = blockIdx.x * blockDim.x + threadIdx.x;
    if (e >= N_EDGES) return;
    int s = g_src[e];
    int d = g_dst[e];
    int slot = atomicAdd(&g_cur[d], 1);
    float nrm = g_dinv[s] * g_dinv[d];
    g_csr[slot] = make_int4(s, d, __float_as_int(nrm), 0);
}

// ---------------- layer 1 GEMM: h1 = x @ W1; agg1 init with self loop ------
__global__ __launch_bounds__(256) void k_gemm1(const float* __restrict__ x,
                                               const float* __restrict__ W1) {
    __shared__ float Ws[IN_DIM * HID_DIM];          // 32 KB
    {
        float4* dsh = (float4*)Ws;
        const float4* ssh = (const float4*)W1;
        for (int i = threadIdx.x; i < IN_DIM * HID_DIM / 4; i += blockDim.x)
            dsh[i] = ssh[i];
    }
    __syncthreads();

    int node = blockIdx.x * blockDim.x + threadIdx.x;
    if (node >= N_NODES) return;

    float acc[HID_DIM];
#pragma unroll
    for (int j = 0; j < HID_DIM; j++) acc[j] = 0.0f;

    const float4* xr = (const float4*)(x + (size_t)node * IN_DIM);
#pragma unroll 2
    for (int kk = 0; kk < IN_DIM / 4; ++kk) {
        float4 xv = xr[kk];
        float xs[4] = {xv.x, xv.y, xv.z, xv.w};
#pragma unroll
        for (int q = 0; q < 4; ++q) {
            const float4* wr = (const float4*)&Ws[(kk * 4 + q) * HID_DIM];
#pragma unroll
            for (int j4 = 0; j4 < HID_DIM / 4; ++j4) {
                float4 w = wr[j4];
                acc[4 * j4 + 0] += xs[q] * w.x;
                acc[4 * j4 + 1] += xs[q] * w.y;
                acc[4 * j4 + 2] += xs[q] * w.z;
                acc[4 * j4 + 3] += xs[q] * w.w;
            }
        }
    }

    float di = g_dinv[node];
    float sl = di * di;                             // self-loop coefficient
    size_t base = (size_t)node * HID_DIM;
#pragma unroll
    for (int j4 = 0; j4 < HID_DIM / 4; ++j4) {
        float4 h;
        h.x = acc[4 * j4 + 0]; h.y = acc[4 * j4 + 1];
        h.z = acc[4 * j4 + 2]; h.w = acc[4 * j4 + 3];
        *(float4*)&g_h1[base + 4 * j4] = h;
        float4 a;
        a.x = h.x * sl; a.y = h.y * sl; a.z = h.z * sl; a.w = h.w * sl;
        *(float4*)&g_agg1[base + 4 * j4] = a;
    }
}

// ---- layer 1 aggregation: 8 sorted edges/thread, segmented pre-combine ----
// thread = (group, chunk): 16 chunks of 4 floats. Entries broadcast across
// the 16 chunk lanes; 8 gathers are independent rows (true MLP-8).
__global__ __launch_bounds__(256) void k_agg1s() {
    int idx = blockIdx.x * blockDim.x + threadIdx.x;
    int g = idx >> 4;
    if (g >= NGROUPS) return;
    int c = (idx & 15) << 2;
    int lo = g * GRP;

    int4 ent[GRP];
#pragma unroll
    for (int j = 0; j < GRP; j++) ent[j] = g_csr[lo + j];
    float4 v[GRP];
#pragma unroll
    for (int j = 0; j < GRP; j++)
        v[j] = __ldg((const float4*)&g_h1[(size_t)ent[j].x * HID_DIM + c]);

    float ax = 0.f, ay = 0.f, az = 0.f, aw = 0.f;
    int cur = ent[0].y;
#pragma unroll
    for (int j = 0; j < GRP; j++) {
        if (ent[j].y != cur) {                      // dst run ended -> flush
            redg_v4(&g_agg1[(size_t)cur * HID_DIM + c], ax, ay, az, aw);
            ax = ay = az = aw = 0.f;
            cur = ent[j].y;
        }
        float nrm = __int_as_float(ent[j].z);
        ax += v[j].x * nrm; ay += v[j].y * nrm;
        az += v[j].z * nrm; aw += v[j].w * nrm;
    }
    redg_v4(&g_agg1[(size_t)cur * HID_DIM + c], ax, ay, az, aw);
}

// ------- layer 2 GEMM: h2 = relu(agg1 + b1) @ W2; out init = h2*d^2 + b2 ---
__global__ __launch_bounds__(256) void k_gemm2(const float* __restrict__ W2,
                                               const float* __restrict__ b1,
                                               const float* __restrict__ b2,
                                               float* __restrict__ out) {
    __shared__ float Ws[HID_DIM * OUT_DIM];         // 10 KB
    __shared__ float b1s[HID_DIM];
    __shared__ float b2s[OUT_DIM];
    for (int i = threadIdx.x; i < HID_DIM * OUT_DIM; i += blockDim.x) Ws[i] = W2[i];
    for (int i = threadIdx.x; i < HID_DIM; i += blockDim.x) b1s[i] = b1[i];
    for (int i = threadIdx.x; i < OUT_DIM; i += blockDim.x) b2s[i] = b2[i];
    __syncthreads();

    int node = blockIdx.x * blockDim.x + threadIdx.x;
    if (node >= N_NODES) return;

    float acc[OUT_DIM];
#pragma unroll
    for (int j = 0; j < OUT_DIM; j++) acc[j] = 0.0f;

    size_t ibase = (size_t)node * HID_DIM;
#pragma unroll 2
    for (int k4 = 0; k4 < HID_DIM / 4; ++k4) {
        float4 a = *(const float4*)&g_agg1[ibase + 4 * k4];
        float vin[4];
        vin[0] = fmaxf(a.x + b1s[4 * k4 + 0], 0.0f);
        vin[1] = fmaxf(a.y + b1s[4 * k4 + 1], 0.0f);
        vin[2] = fmaxf(a.z + b1s[4 * k4 + 2], 0.0f);
        vin[3] = fmaxf(a.w + b1s[4 * k4 + 3], 0.0f);
#pragma unroll
        for (int q = 0; q < 4; ++q) {
            const float4* wr = (const float4*)&Ws[(4 * k4 + q) * OUT_DIM];
#pragma unroll
            for (int j4 = 0; j4 < OUT_DIM / 4; ++j4) {
                float4 w = wr[j4];
                acc[4 * j4 + 0] += vin[q] * w.x;
                acc[4 * j4 + 1] += vin[q] * w.y;
                acc[4 * j4 + 2] += vin[q] * w.z;
                acc[4 * j4 + 3] += vin[q] * w.w;
            }
        }
    }

    float di = g_dinv[node];
    float sl = di * di;
    size_t ob = (size_t)node * OUT_DIM;
#pragma unroll
    for (int j4 = 0; j4 < OUT_DIM / 4; ++j4) {
        float4 h;
        h.x = acc[4 * j4 + 0]; h.y = acc[4 * j4 + 1];
        h.z = acc[4 * j4 + 2]; h.w = acc[4 * j4 + 3];
        *(float4*)&g_h2[ob + 4 * j4] = h;
        float4 o;
        o.x = h.x * sl + b2s[4 * j4 + 0];
        o.y = h.y * sl + b2s[4 * j4 + 1];
        o.z = h.z * sl + b2s[4 * j4 + 2];
        o.w = h.w * sl + b2s[4 * j4 + 3];
        *(float4*)&out[ob + 4 * j4] = o;
    }
}

// ---- layer 2 aggregation: 8 sorted edges/thread, 10 chunks ---------------
__global__ __launch_bounds__(250) void k_agg2s(float* __restrict__ out) {
    int idx = blockIdx.x * blockDim.x + threadIdx.x;
    int g = idx / 10;
    if (g >= NGROUPS) return;
    int c = (idx - g * 10) * 4;
    int lo = g * GRP;

    int4 ent[GRP];
#pragma unroll
    for (int j = 0; j < GRP; j++) ent[j] = g_csr[lo + j];
    float4 v[GRP];
#pragma unroll
    for (int j = 0; j < GRP; j++)
        v[j] = __ldg((const float4*)&g_h2[(size_t)ent[j].x * OUT_DIM + c]);

    float ax = 0.f, ay = 0.f, az = 0.f, aw = 0.f;
    int cur = ent[0].y;
#pragma unroll
    for (int j = 0; j < GRP; j++) {
        if (ent[j].y != cur) {
            redg_v4(&out[(size_t)cur * OUT_DIM + c], ax, ay, az, aw);
            ax = ay = az = aw = 0.f;
            cur = ent[j].y;
        }
        float nrm = __int_as_float(ent[j].z);
        ax += v[j].x * nrm; ay += v[j].y * nrm;
        az += v[j].z * nrm; aw += v[j].w * nrm;
    }
    redg_v4(&out[(size_t)cur * OUT_DIM + c], ax, ay, az, aw);
}

// ---------------- launcher -------------------------------------------------
extern "C" void kernel_launch(void* const* d_in, const int* in_sizes, int n_in,
                              void* d_out, int out_size) {
    const float*    x  = (const float*)d_in[0];
    const unsigned* ei = (const unsigned*)d_in[1];   // int32 OR int64 words
    const float*    W1 = (const float*)d_in[2];
    const float*    b1 = (const float*)d_in[3];
    const float*    W2 = (const float*)d_in[4];
    const float*    b2 = (const float*)d_in[5];
    float* out = (float*)d_out;

    const int T = 256;
    k_detect  <<<1, 32>>>(ei);
    k_zero_cnt<<<(N_NODES + T - 1) / T, T>>>();
    k_extract <<<(N_EDGES + T - 1) / T, T>>>(ei);
    k_rsqrt   <<<(N_NODES + T - 1) / T, T>>>();
    k_scan    <<<1, SCAN_T>>>();
    k_fill    <<<(N_EDGES + T - 1) / T, T>>>();
    k_gemm1   <<<(N_NODES + T - 1) / T, T>>>(x, W1);
    k_agg1s   <<<(NGROUPS * 16 + T - 1) / T, T>>>();
    k_gemm2   <<<(N_NODES + T - 1) / T, T>>>(W2, b1, b2, out);
    k_agg2s   <<<(NGROUPS * 10 + 249) / 250, 250>>>(out);
}

// round 12
// speedup vs baseline: 1.3133x; 1.3133x over previous
#include <cuda_runtime.h>
#include <cuda_bf16.h>

#define N_NODES 100000
#define N_EDGES 1600000
#define IN_DIM  128
#define HID_DIM 64
#define OUT_DIM 40

// ---------------- scratch (static device globals; no runtime alloc) --------
__device__              int    g_is64;
__device__              int    g_cnt [N_NODES];      // in-degree (edges only)
__device__ __align__(16) float g_dinv[N_NODES];
__device__              int    g_src [N_EDGES];
__device__              int    g_dst [N_EDGES];
__device__ __align__(16) int4  g_em  [N_EDGES];      // {src, dst, bits(norm), 0}
__device__ __align__(16) float g_h1  [(size_t)N_NODES * HID_DIM];   // x@W1
__device__ __align__(16) float g_agg1[(size_t)N_NODES * HID_DIM];   // layer1 agg
__device__ __align__(16) float g_h2  [(size_t)N_NODES * OUT_DIM];   // relu(agg1+b1)@W2

__device__ __forceinline__ void redg_v4(float* p, float a, float b, float c, float d) {
    asm volatile("red.global.add.v4.f32 [%0], {%1, %2, %3, %4};"
                 :: "l"(p), "f"(a), "f"(b), "f"(c), "f"(d) : "memory");
}

// ---------------- dtype detection: int32 vs int64 edge_index ---------------
__global__ void k_detect(const unsigned* __restrict__ w) {
    if (threadIdx.x == 0 && blockIdx.x == 0) {
        int all0 = 1;
        for (int i = 0; i < 64; i++)
            if (w[2 * i + 1] != 0u) { all0 = 0; break; }
        g_is64 = all0;
    }
}

__global__ void k_zero_cnt() {
    int i = blockIdx.x * blockDim.x + threadIdx.x;
    if (i < N_NODES) g_cnt[i] = 0;
}

// extract src/dst as int32 (either stored width) + histogram by dst
__global__ void k_extract(const unsigned* __restrict__ w) {
    int e = blockIdx.x * blockDim.x + threadIdx.x;
    if (e >= N_EDGES) return;
    int s, d;
    if (g_is64) {
        s = (int)w[2 * e];                           // low word of int64
        d = (int)w[2 * (N_EDGES + e)];
    } else {
        s = (int)w[e];
        d = (int)w[N_EDGES + e];
    }
    g_src[e] = s;
    g_dst[e] = d;
    atomicAdd(&g_cnt[d], 1);                         // int REDG
}

__global__ void k_rsqrt() {
    int i = blockIdx.x * blockDim.x + threadIdx.x;
    if (i < N_NODES) g_dinv[i] = rsqrtf((float)g_cnt[i] + 1.0f);   // + self loop
}

// pack {src, dst, norm} into one int4 per edge (replaces k_norm pass)
__global__ void k_em() {
    int e = blockIdx.x * blockDim.x + threadIdx.x;
    if (e >= N_EDGES) return;
    int s = g_src[e];
    int d = g_dst[e];
    float nrm = g_dinv[s] * g_dinv[d];
    g_em[e] = make_int4(s, d, __float_as_int(nrm), 0);
}

// ---------------- layer 1 GEMM: h1 = x @ W1; agg1 init with self loop ------
__global__ __launch_bounds__(256) void k_gemm1(const float* __restrict__ x,
                                               const float* __restrict__ W1) {
    __shared__ float Ws[IN_DIM * HID_DIM];          // 32 KB
    {
        float4* dsh = (float4*)Ws;
        const float4* ssh = (const float4*)W1;
        for (int i = threadIdx.x; i < IN_DIM * HID_DIM / 4; i += blockDim.x)
            dsh[i] = ssh[i];
    }
    __syncthreads();

    int node = blockIdx.x * blockDim.x + threadIdx.x;
    if (node >= N_NODES) return;

    float acc[HID_DIM];
#pragma unroll
    for (int j = 0; j < HID_DIM; j++) acc[j] = 0.0f;

    const float4* xr = (const float4*)(x + (size_t)node * IN_DIM);
#pragma unroll 2
    for (int kk = 0; kk < IN_DIM / 4; ++kk) {
        float4 xv = xr[kk];
        float xs[4] = {xv.x, xv.y, xv.z, xv.w};
#pragma unroll
        for (int q = 0; q < 4; ++q) {
            const float4* wr = (const float4*)&Ws[(kk * 4 + q) * HID_DIM];
#pragma unroll
            for (int j4 = 0; j4 < HID_DIM / 4; ++j4) {
                float4 w = wr[j4];                  // warp-broadcast LDS
                acc[4 * j4 + 0] += xs[q] * w.x;
                acc[4 * j4 + 1] += xs[q] * w.y;
                acc[4 * j4 + 2] += xs[q] * w.z;
                acc[4 * j4 + 3] += xs[q] * w.w;
            }
        }
    }

    float di = g_dinv[node];
    float sl = di * di;                             // self-loop coefficient
    size_t base = (size_t)node * HID_DIM;
#pragma unroll
    for (int j4 = 0; j4 < HID_DIM / 4; ++j4) {
        float4 h;
        h.x = acc[4 * j4 + 0]; h.y = acc[4 * j4 + 1];
        h.z = acc[4 * j4 + 2]; h.w = acc[4 * j4 + 3];
        *(float4*)&g_h1[base + 4 * j4] = h;
        float4 a;
        a.x = h.x * sl; a.y = h.y * sl; a.z = h.z * sl; a.w = h.w * sl;
        *(float4*)&g_agg1[base + 4 * j4] = a;
    }
}

// ------- layer 1 edge aggregation: 16 threads/edge, vector REDG.128 --------
__global__ __launch_bounds__(256) void k_agg1() {
    int idx = blockIdx.x * blockDim.x + threadIdx.x;    // E * 16 items
    if (idx >= N_EDGES * 16) return;
    int e = idx >> 4;
    int c = (idx & 15) << 2;                            // float offset, 16B aligned
    int4 em = g_em[e];                                  // one broadcast LDG.128
    float nrm = __int_as_float(em.z);
    float4 v = *(const float4*)&g_h1[(size_t)em.x * HID_DIM + c];
    float* p = &g_agg1[(size_t)em.y * HID_DIM + c];
    redg_v4(p, v.x * nrm, v.y * nrm, v.z * nrm, v.w * nrm);
}

// ------- layer 2 GEMM: h2 = relu(agg1 + b1) @ W2; out init = h2*d^2 + b2 ---
__global__ __launch_bounds__(256) void k_gemm2(const float* __restrict__ W2,
                                               const float* __restrict__ b1,
                                               const float* __restrict__ b2,
                                               float* __restrict__ out) {
    __shared__ float Ws[HID_DIM * OUT_DIM];         // 10 KB
    __shared__ float b1s[HID_DIM];
    __shared__ float b2s[OUT_DIM];
    for (int i = threadIdx.x; i < HID_DIM * OUT_DIM; i += blockDim.x) Ws[i] = W2[i];
    for (int i = threadIdx.x; i < HID_DIM; i += blockDim.x) b1s[i] = b1[i];
    for (int i = threadIdx.x; i < OUT_DIM; i += blockDim.x) b2s[i] = b2[i];
    __syncthreads();

    int node = blockIdx.x * blockDim.x + threadIdx.x;
    if (node >= N_NODES) return;

    float acc[OUT_DIM];
#pragma unroll
    for (int j = 0; j < OUT_DIM; j++) acc[j] = 0.0f;

    size_t ibase = (size_t)node * HID_DIM;
#pragma unroll 2
    for (int k4 = 0; k4 < HID_DIM / 4; ++k4) {
        float4 a = *(const float4*)&g_agg1[ibase + 4 * k4];
        float vin[4];
        vin[0] = fmaxf(a.x + b1s[4 * k4 + 0], 0.0f);
        vin[1] = fmaxf(a.y + b1s[4 * k4 + 1], 0.0f);
        vin[2] = fmaxf(a.z + b1s[4 * k4 + 2], 0.0f);
        vin[3] = fmaxf(a.w + b1s[4 * k4 + 3], 0.0f);
#pragma unroll
        for (int q = 0; q < 4; ++q) {
            const float4* wr = (const float4*)&Ws[(4 * k4 + q) * OUT_DIM];
#pragma unroll
            for (int j4 = 0; j4 < OUT_DIM / 4; ++j4) {
                float4 w = wr[j4];
                acc[4 * j4 + 0] += vin[q] * w.x;
                acc[4 * j4 + 1] += vin[q] * w.y;
                acc[4 * j4 + 2] += vin[q] * w.z;
                acc[4 * j4 + 3] += vin[q] * w.w;
            }
        }
    }

    float di = g_dinv[node];
    float sl = di * di;
    size_t ob = (size_t)node * OUT_DIM;
#pragma unroll
    for (int j4 = 0; j4 < OUT_DIM / 4; ++j4) {
        float4 h;
        h.x = acc[4 * j4 + 0]; h.y = acc[4 * j4 + 1];
        h.z = acc[4 * j4 + 2]; h.w = acc[4 * j4 + 3];
        *(float4*)&g_h2[ob + 4 * j4] = h;
        float4 o;
        o.x = h.x * sl + b2s[4 * j4 + 0];
        o.y = h.y * sl + b2s[4 * j4 + 1];
        o.z = h.z * sl + b2s[4 * j4 + 2];
        o.w = h.w * sl + b2s[4 * j4 + 3];
        *(float4*)&out[ob + 4 * j4] = o;
    }
}

// ------- layer 2 edge aggregation: 10 threads/edge -------------------------
__global__ __launch_bounds__(250) void k_agg2(float* __restrict__ out) {
    int idx = blockIdx.x * blockDim.x + threadIdx.x;    // E * 10 items
    int e = idx / 10;
    if (e >= N_EDGES) return;
    int c = (idx - e * 10) * 4;                         // float offset, 16B aligned
    int4 em = g_em[e];                                  // one broadcast LDG.128
    float nrm = __int_as_float(em.z);
    float4 v = *(const float4*)&g_h2[(size_t)em.x * OUT_DIM + c];
    float* p = &out[(size_t)em.y * OUT_DIM + c];
    redg_v4(p, v.x * nrm, v.y * nrm, v.z * nrm, v.w * nrm);
}

// ---------------- launcher -------------------------------------------------
extern "C" void kernel_launch(void* const* d_in, const int* in_sizes, int n_in,
                              void* d_out, int out_size) {
    const float*    x  = (const float*)d_in[0];
    const unsigned* ei = (const unsigned*)d_in[1];   // int32 OR int64 words
    const float*    W1 = (const float*)d_in[2];
    const float*    b1 = (const float*)d_in[3];
    const float*    W2 = (const float*)d_in[4];
    const float*    b2 = (const float*)d_in[5];
    float* out = (float*)d_out;

    const int T = 256;
    k_detect  <<<1, 32>>>(ei);
    k_zero_cnt<<<(N_NODES + T - 1) / T, T>>>();
    k_extract <<<(N_EDGES + T - 1) / T, T>>>(ei);
    k_rsqrt   <<<(N_NODES + T - 1) / T, T>>>();
    k_em      <<<(N_EDGES + T - 1) / T, T>>>();
    k_gemm1   <<<(N_NODES + T - 1) / T, T>>>(x, W1);
    k_agg1    <<<(N_EDGES * 16 + T - 1) / T, T>>>();
    k_gemm2   <<<(N_NODES + T - 1) / T, T>>>(W2, b1, b2, out);
    k_agg2    <<<(N_EDGES * 10 + 249) / 250, 250>>>(out);
}